// round 2
// baseline (speedup 1.0000x reference)
#include <cuda_runtime.h>
#include <cuda_bf16.h>
#include <math.h>

// Problem constants (fixed by the dataset)
#define BATCH 16
#define LQ    1024
#define EMBED 768
#define NH    12
#define NL    3
#define NP    4
#define DV    384
#define DH    32
#define LKV   5376
#define NOFF  (NH*NL*NP*2)   // 288
#define NAW   (NH*NL*NP)     // 144
#define RQ    (BATCH*LQ)     // 16384
#define RKV   (BATCH*LKV)    // 86016

// ---------------- scratch (device globals; no allocation allowed) ----------------
__device__ float g_stats_q [RQ  * 2];
__device__ float g_stats_kv[RKV * 2];
__device__ float g_value [RKV * (size_t)DV];     // (B,LKV,NH,DH) flattened, 132 MB
__device__ float g_offraw[RQ  * (size_t)NOFF];
__device__ float g_awraw [RQ  * (size_t)NAW];
__device__ float g_attn  [RQ  * (size_t)DV];

// ---------------- row mean/rstd (warp per row) ----------------
__global__ __launch_bounds__(256) void row_stats(const float* __restrict__ X,
                                                 float* __restrict__ stats, int rows) {
    int row  = blockIdx.x * 8 + (threadIdx.x >> 5);
    int lane = threadIdx.x & 31;
    if (row >= rows) return;
    const float* x = X + (size_t)row * EMBED;
    float s = 0.f, ss = 0.f;
    #pragma unroll
    for (int i = lane; i < EMBED; i += 32) { float v = x[i]; s += v; ss = fmaf(v, v, ss); }
    #pragma unroll
    for (int o = 16; o; o >>= 1) {
        s  += __shfl_xor_sync(0xffffffffu, s,  o);
        ss += __shfl_xor_sync(0xffffffffu, ss, o);
    }
    if (lane == 0) {
        float mu  = s * (1.f / EMBED);
        float var = ss * (1.f / EMBED) - mu * mu;
        stats[row*2]   = mu;
        stats[row*2+1] = rsqrtf(var + 1e-6f);
    }
}

// ---------------- generic SGEMM with fused LN on A and fused residual epilogue ----
// C[M,N] = epilogue( LN?(A)[M,K] @ Bm[K,N] + bias[N] )
// LN?(A)[m,k] = (A[m,k]-mu[m])*rstd[m]*lnw[k] + lnb[k]  when stats != nullptr
// epilogue: if resid: C = resid + gamma[n]*(acc+bias) else C = acc+bias
#define BM 64
#define BN 64
#define BK 16

__global__ __launch_bounds__(256) void gemm_ln(
    const float* __restrict__ A, const float* __restrict__ stats,
    const float* __restrict__ lnw, const float* __restrict__ lnb,
    const float* __restrict__ Bm, const float* __restrict__ bias,
    float* __restrict__ C, int M, int N, int K,
    const float* __restrict__ resid, const float* __restrict__ gamma)
{
    __shared__ float As[BK][BM + 4];
    __shared__ float Bs[BK][BN + 4];

    const int t  = threadIdx.x;           // 256 threads
    const int m0 = blockIdx.y * BM;
    const int n0 = blockIdx.x * BN;
    const int tx = t & 15;                // n dir
    const int ty = t >> 4;                // m dir

    // A-tile load mapping: 64 rows x 16 k, float4 along k
    const int am = t >> 2;                // 0..63
    const int ak = (t & 3) * 4;           // 0,4,8,12
    // B-tile load mapping: 16 k x 64 n, float4 along n
    const int bk = t >> 4;                // 0..15
    const int bn = (t & 15) * 4;

    const bool hasln = (stats != nullptr);
    float mu = 0.f, rstd = 1.f;
    if (hasln) { mu = stats[(m0 + am)*2]; rstd = stats[(m0 + am)*2 + 1]; }
    const float* Arow = A + (size_t)(m0 + am) * K;

    float acc[4][4] = {};

    for (int k0 = 0; k0 < K; k0 += BK) {
        float4 a = *(const float4*)(Arow + k0 + ak);
        if (hasln) {
            float4 w  = *(const float4*)(lnw + k0 + ak);
            float4 bb = *(const float4*)(lnb + k0 + ak);
            a.x = fmaf((a.x - mu) * rstd, w.x, bb.x);
            a.y = fmaf((a.y - mu) * rstd, w.y, bb.y);
            a.z = fmaf((a.z - mu) * rstd, w.z, bb.z);
            a.w = fmaf((a.w - mu) * rstd, w.w, bb.w);
        }
        As[ak+0][am] = a.x; As[ak+1][am] = a.y; As[ak+2][am] = a.z; As[ak+3][am] = a.w;

        float4 b4 = make_float4(0.f, 0.f, 0.f, 0.f);
        if (n0 + bn < N) b4 = *(const float4*)(Bm + (size_t)(k0 + bk) * N + n0 + bn);
        *(float4*)&Bs[bk][bn] = b4;

        __syncthreads();
        #pragma unroll
        for (int kk = 0; kk < BK; ++kk) {
            float4 ra = *(const float4*)(&As[kk][ty * 4]);
            float4 rb = *(const float4*)(&Bs[kk][tx * 4]);
            float rm[4] = {ra.x, ra.y, ra.z, ra.w};
            float rn[4] = {rb.x, rb.y, rb.z, rb.w};
            #pragma unroll
            for (int i = 0; i < 4; ++i)
                #pragma unroll
                for (int j = 0; j < 4; ++j)
                    acc[i][j] = fmaf(rm[i], rn[j], acc[i][j]);
        }
        __syncthreads();
    }

    #pragma unroll
    for (int i = 0; i < 4; ++i) {
        int m = m0 + ty * 4 + i;
        #pragma unroll
        for (int j = 0; j < 4; ++j) {
            int n = n0 + tx * 4 + j;
            if (n < N) {
                float v = acc[i][j] + bias[n];
                if (resid) v = resid[(size_t)m * N + n] + gamma[n] * v;
                C[(size_t)m * N + n] = v;
            }
        }
    }
}

// ---------------- MS-deformable sampling: one block per query, warp per head ------
__device__ __forceinline__ float fetchv(const float* __restrict__ vb, int st,
                                        int xi, int yi, int W, int H) {
    if (xi < 0 || xi >= W || yi < 0 || yi >= H) return 0.f;
    return __ldg(vb + (size_t)(st + yi * W + xi) * DV);
}

__global__ __launch_bounds__(NH * 32) void msda_sample(
    const float* __restrict__ offraw, const float* __restrict__ awraw,
    const float* __restrict__ ref, const int* __restrict__ shapes,
    const int* __restrict__ lstart, const float* __restrict__ value,
    float* __restrict__ attn)
{
    const int r    = blockIdx.x;          // b*LQ + q
    const int h    = threadIdx.x >> 5;    // head 0..11
    const int lane = threadIdx.x & 31;    // channel d
    const int b    = r / LQ;

    // softmax over 12 attention logits of this head (lane j < 12 holds value j)
    float a = (lane < NL * NP) ? awraw[(size_t)r * NAW + h * (NL * NP) + lane] : -INFINITY;
    float mx = a;
    #pragma unroll
    for (int o = 16; o; o >>= 1) mx = fmaxf(mx, __shfl_xor_sync(0xffffffffu, mx, o));
    float e = (lane < NL * NP) ? expf(a - mx) : 0.f;
    float se = e;
    #pragma unroll
    for (int o = 16; o; o >>= 1) se += __shfl_xor_sync(0xffffffffu, se, o);
    float wgt = e / se;

    // preload 24 offsets (lane k < 24) and 6 ref coords (lane k < 6)
    float off = (lane < NL * NP * 2) ? offraw[(size_t)r * NOFF + h * (NL * NP * 2) + lane] : 0.f;
    float rp  = (lane < NL * 2)      ? ref[(size_t)r * (NL * 2) + lane] : 0.f;

    const float* vb = value + (size_t)b * LKV * DV + h * DH + lane;
    float acc = 0.f;

    #pragma unroll
    for (int l = 0; l < NL; ++l) {
        const int Hl = shapes[l * 2 + 0];
        const int Wl = shapes[l * 2 + 1];
        const int st = lstart[l];
        const float rx = __shfl_sync(0xffffffffu, rp, l * 2 + 0);
        const float ry = __shfl_sync(0xffffffffu, rp, l * 2 + 1);
        const float fW = (float)Wl, fH = (float)Hl;
        #pragma unroll
        for (int p = 0; p < NP; ++p) {
            const int j = l * NP + p;
            const float ox = __shfl_sync(0xffffffffu, off, j * 2 + 0);
            const float oy = __shfl_sync(0xffffffffu, off, j * 2 + 1);
            const float w_ = __shfl_sync(0xffffffffu, wgt, j);

            const float x = (rx + ox / fW) * fW - 0.5f;
            const float y = (ry + oy / fH) * fH - 0.5f;
            const float xf = floorf(x), yf = floorf(y);
            const int   x0 = (int)xf,   y0 = (int)yf;
            const float dx = x - xf,    dy = y - yf;

            const float g00 = fetchv(vb, st, x0,     y0,     Wl, Hl);
            const float g01 = fetchv(vb, st, x0 + 1, y0,     Wl, Hl);
            const float g10 = fetchv(vb, st, x0,     y0 + 1, Wl, Hl);
            const float g11 = fetchv(vb, st, x0 + 1, y0 + 1, Wl, Hl);

            const float s = (1.f - dx) * (1.f - dy) * g00 + dx * (1.f - dy) * g01 +
                            (1.f - dx) * dy * g10 + dx * dy * g11;
            acc = fmaf(w_, s, acc);
        }
    }
    attn[(size_t)r * DV + h * DH + lane] = acc;
}

// ---------------- launch ----------------
extern "C" void kernel_launch(void* const* d_in, const int* in_sizes, int n_in,
                              void* d_out, int out_size) {
    const float* q      = (const float*)d_in[0];
    const float* ref    = (const float*)d_in[1];
    const float* kv     = (const float*)d_in[2];
    const int*   shapes = (const int*)  d_in[3];
    const int*   lstart = (const int*)  d_in[4];
    const float* ln1w   = (const float*)d_in[5];
    const float* ln1b   = (const float*)d_in[6];
    const float* ln2w   = (const float*)d_in[7];
    const float* ln2b   = (const float*)d_in[8];
    const float* gamma  = (const float*)d_in[9];
    const float* w_off  = (const float*)d_in[10];
    const float* b_off  = (const float*)d_in[11];
    const float* w_aw   = (const float*)d_in[12];
    const float* b_aw   = (const float*)d_in[13];
    const float* w_val  = (const float*)d_in[14];
    const float* b_val  = (const float*)d_in[15];
    const float* w_out  = (const float*)d_in[16];
    const float* b_out  = (const float*)d_in[17];
    float* out = (float*)d_out;

    float *p_sq, *p_skv, *p_val, *p_off, *p_aw, *p_attn;
    cudaGetSymbolAddress((void**)&p_sq,   g_stats_q);
    cudaGetSymbolAddress((void**)&p_skv,  g_stats_kv);
    cudaGetSymbolAddress((void**)&p_val,  g_value);
    cudaGetSymbolAddress((void**)&p_off,  g_offraw);
    cudaGetSymbolAddress((void**)&p_aw,   g_awraw);
    cudaGetSymbolAddress((void**)&p_attn, g_attn);

    // 1) LN row stats
    row_stats<<<RQ  / 8, 256>>>(q,  p_sq,  RQ);
    row_stats<<<RKV / 8, 256>>>(kv, p_skv, RKV);

    // 2) value = LN(kv) @ w_val + b_val   (86016 x 384, K=768)
    gemm_ln<<<dim3(DV / BN, RKV / BM), 256>>>(
        kv, p_skv, ln2w, ln2b, w_val, b_val, p_val, RKV, DV, EMBED, nullptr, nullptr);

    // 3) offraw = LN(q) @ w_off + b_off   (16384 x 288, K=768)
    gemm_ln<<<dim3((NOFF + BN - 1) / BN, RQ / BM), 256>>>(
        q, p_sq, ln1w, ln1b, w_off, b_off, p_off, RQ, NOFF, EMBED, nullptr, nullptr);

    // 4) awraw = LN(q) @ w_aw + b_aw      (16384 x 144, K=768)
    gemm_ln<<<dim3((NAW + BN - 1) / BN, RQ / BM), 256>>>(
        q, p_sq, ln1w, ln1b, w_aw, b_aw, p_aw, RQ, NAW, EMBED, nullptr, nullptr);

    // 5) deformable sampling -> attn (16384 x 384)
    msda_sample<<<RQ, NH * 32>>>(p_off, p_aw, ref, shapes, lstart, p_val, p_attn);

    // 6) out = q + gamma * (attn @ w_out + b_out)   (16384 x 768, K=384)
    gemm_ln<<<dim3(EMBED / BN, RQ / BM), 256>>>(
        p_attn, nullptr, nullptr, nullptr, w_out, b_out, out, RQ, EMBED, DV, q, gamma);
}

// round 3
// speedup vs baseline: 1.0004x; 1.0004x over previous
#include <cuda_runtime.h>
#include <cuda_bf16.h>
#include <math.h>

// Problem constants (fixed by the dataset)
#define BATCH 16
#define LQ    1024
#define EMBED 768
#define NH    12
#define NL    3
#define NP    4
#define DV    384
#define DH    32
#define LKV   5376
#define NOFF  (NH*NL*NP*2)   // 288
#define NAW   (NH*NL*NP)     // 144
#define RQ    (BATCH*LQ)     // 16384
#define RKV   (BATCH*LKV)    // 86016

// ---------------- scratch (device globals; no allocation allowed) ----------------
__device__ float g_stats_q [RQ  * 2];
__device__ float g_stats_kv[RKV * 2];
__device__ float g_value [RKV * (size_t)DV];     // (B,LKV,NH,DH) flattened, 132 MB
__device__ float g_offraw[RQ  * (size_t)NOFF];
__device__ float g_awraw [RQ  * (size_t)NAW];
__device__ float g_attn  [RQ  * (size_t)DV];

// ---------------- row mean/rstd (warp per row) ----------------
__global__ __launch_bounds__(256) void row_stats(const float* __restrict__ X,
                                                 float* __restrict__ stats, int rows) {
    int row  = blockIdx.x * 8 + (threadIdx.x >> 5);
    int lane = threadIdx.x & 31;
    if (row >= rows) return;
    const float* x = X + (size_t)row * EMBED;
    float s = 0.f, ss = 0.f;
    #pragma unroll
    for (int i = lane; i < EMBED; i += 32) { float v = x[i]; s += v; ss = fmaf(v, v, ss); }
    #pragma unroll
    for (int o = 16; o; o >>= 1) {
        s  += __shfl_xor_sync(0xffffffffu, s,  o);
        ss += __shfl_xor_sync(0xffffffffu, ss, o);
    }
    if (lane == 0) {
        float mu  = s * (1.f / EMBED);
        float var = ss * (1.f / EMBED) - mu * mu;
        stats[row*2]   = mu;
        stats[row*2+1] = rsqrtf(var + 1e-6f);
    }
}

// ---------------- generic SGEMM with fused LN on A and fused residual epilogue ----
// C[M,N] = epilogue( LN?(A)[M,K] @ Bm[K,N] + bias[N] )
// LN?(A)[m,k] = (A[m,k]-mu[m])*rstd[m]*lnw[k] + lnb[k]  when stats != nullptr
// epilogue: if resid: C = resid + gamma[n]*(acc+bias) else C = acc+bias
#define BM 64
#define BN 64
#define BK 16

__global__ __launch_bounds__(256) void gemm_ln(
    const float* __restrict__ A, const float* __restrict__ stats,
    const float* __restrict__ lnw, const float* __restrict__ lnb,
    const float* __restrict__ Bm, const float* __restrict__ bias,
    float* __restrict__ C, int M, int N, int K,
    const float* __restrict__ resid, const float* __restrict__ gamma)
{
    __shared__ float As[BK][BM + 4];
    __shared__ float Bs[BK][BN + 4];

    const int t  = threadIdx.x;           // 256 threads
    const int m0 = blockIdx.y * BM;
    const int n0 = blockIdx.x * BN;
    const int tx = t & 15;                // n dir
    const int ty = t >> 4;                // m dir

    // A-tile load mapping: 64 rows x 16 k, float4 along k
    const int am = t >> 2;                // 0..63
    const int ak = (t & 3) * 4;           // 0,4,8,12
    // B-tile load mapping: 16 k x 64 n, float4 along n
    const int bk = t >> 4;                // 0..15
    const int bn = (t & 15) * 4;

    const bool hasln = (stats != nullptr);
    float mu = 0.f, rstd = 1.f;
    if (hasln) { mu = stats[(m0 + am)*2]; rstd = stats[(m0 + am)*2 + 1]; }
    const float* Arow = A + (size_t)(m0 + am) * K;

    float acc[4][4] = {};

    for (int k0 = 0; k0 < K; k0 += BK) {
        float4 a = *(const float4*)(Arow + k0 + ak);
        if (hasln) {
            float4 w  = *(const float4*)(lnw + k0 + ak);
            float4 bb = *(const float4*)(lnb + k0 + ak);
            a.x = fmaf((a.x - mu) * rstd, w.x, bb.x);
            a.y = fmaf((a.y - mu) * rstd, w.y, bb.y);
            a.z = fmaf((a.z - mu) * rstd, w.z, bb.z);
            a.w = fmaf((a.w - mu) * rstd, w.w, bb.w);
        }
        As[ak+0][am] = a.x; As[ak+1][am] = a.y; As[ak+2][am] = a.z; As[ak+3][am] = a.w;

        float4 b4 = make_float4(0.f, 0.f, 0.f, 0.f);
        if (n0 + bn < N) b4 = *(const float4*)(Bm + (size_t)(k0 + bk) * N + n0 + bn);
        *(float4*)&Bs[bk][bn] = b4;

        __syncthreads();
        #pragma unroll
        for (int kk = 0; kk < BK; ++kk) {
            float4 ra = *(const float4*)(&As[kk][ty * 4]);
            float4 rb = *(const float4*)(&Bs[kk][tx * 4]);
            float rm[4] = {ra.x, ra.y, ra.z, ra.w};
            float rn[4] = {rb.x, rb.y, rb.z, rb.w};
            #pragma unroll
            for (int i = 0; i < 4; ++i)
                #pragma unroll
                for (int j = 0; j < 4; ++j)
                    acc[i][j] = fmaf(rm[i], rn[j], acc[i][j]);
        }
        __syncthreads();
    }

    #pragma unroll
    for (int i = 0; i < 4; ++i) {
        int m = m0 + ty * 4 + i;
        #pragma unroll
        for (int j = 0; j < 4; ++j) {
            int n = n0 + tx * 4 + j;
            if (n < N) {
                float v = acc[i][j] + bias[n];
                if (resid) v = resid[(size_t)m * N + n] + gamma[n] * v;
                C[(size_t)m * N + n] = v;
            }
        }
    }
}

// ---------------- MS-deformable sampling: one block per query, warp per head ------
__device__ __forceinline__ float fetchv(const float* __restrict__ vb, int st,
                                        int xi, int yi, int W, int H) {
    if (xi < 0 || xi >= W || yi < 0 || yi >= H) return 0.f;
    return __ldg(vb + (size_t)(st + yi * W + xi) * DV);
}

__global__ __launch_bounds__(NH * 32) void msda_sample(
    const float* __restrict__ offraw, const float* __restrict__ awraw,
    const float* __restrict__ ref, const int* __restrict__ shapes,
    const int* __restrict__ lstart, const float* __restrict__ value,
    float* __restrict__ attn)
{
    const int r    = blockIdx.x;          // b*LQ + q
    const int h    = threadIdx.x >> 5;    // head 0..11
    const int lane = threadIdx.x & 31;    // channel d
    const int b    = r / LQ;

    // softmax over 12 attention logits of this head (lane j < 12 holds value j)
    float a = (lane < NL * NP) ? awraw[(size_t)r * NAW + h * (NL * NP) + lane] : -INFINITY;
    float mx = a;
    #pragma unroll
    for (int o = 16; o; o >>= 1) mx = fmaxf(mx, __shfl_xor_sync(0xffffffffu, mx, o));
    float e = (lane < NL * NP) ? expf(a - mx) : 0.f;
    float se = e;
    #pragma unroll
    for (int o = 16; o; o >>= 1) se += __shfl_xor_sync(0xffffffffu, se, o);
    float wgt = e / se;

    // preload 24 offsets (lane k < 24) and 6 ref coords (lane k < 6)
    float off = (lane < NL * NP * 2) ? offraw[(size_t)r * NOFF + h * (NL * NP * 2) + lane] : 0.f;
    float rp  = (lane < NL * 2)      ? ref[(size_t)r * (NL * 2) + lane] : 0.f;

    const float* vb = value + (size_t)b * LKV * DV + h * DH + lane;
    float acc = 0.f;

    #pragma unroll
    for (int l = 0; l < NL; ++l) {
        const int Hl = shapes[l * 2 + 0];
        const int Wl = shapes[l * 2 + 1];
        const int st = lstart[l];
        const float rx = __shfl_sync(0xffffffffu, rp, l * 2 + 0);
        const float ry = __shfl_sync(0xffffffffu, rp, l * 2 + 1);
        const float fW = (float)Wl, fH = (float)Hl;
        #pragma unroll
        for (int p = 0; p < NP; ++p) {
            const int j = l * NP + p;
            const float ox = __shfl_sync(0xffffffffu, off, j * 2 + 0);
            const float oy = __shfl_sync(0xffffffffu, off, j * 2 + 1);
            const float w_ = __shfl_sync(0xffffffffu, wgt, j);

            const float x = (rx + ox / fW) * fW - 0.5f;
            const float y = (ry + oy / fH) * fH - 0.5f;
            const float xf = floorf(x), yf = floorf(y);
            const int   x0 = (int)xf,   y0 = (int)yf;
            const float dx = x - xf,    dy = y - yf;

            const float g00 = fetchv(vb, st, x0,     y0,     Wl, Hl);
            const float g01 = fetchv(vb, st, x0 + 1, y0,     Wl, Hl);
            const float g10 = fetchv(vb, st, x0,     y0 + 1, Wl, Hl);
            const float g11 = fetchv(vb, st, x0 + 1, y0 + 1, Wl, Hl);

            const float s = (1.f - dx) * (1.f - dy) * g00 + dx * (1.f - dy) * g01 +
                            (1.f - dx) * dy * g10 + dx * dy * g11;
            acc = fmaf(w_, s, acc);
        }
    }
    attn[(size_t)r * DV + h * DH + lane] = acc;
}

// ---------------- launch ----------------
extern "C" void kernel_launch(void* const* d_in, const int* in_sizes, int n_in,
                              void* d_out, int out_size) {
    const float* q      = (const float*)d_in[0];
    const float* ref    = (const float*)d_in[1];
    const float* kv     = (const float*)d_in[2];
    const int*   shapes = (const int*)  d_in[3];
    const int*   lstart = (const int*)  d_in[4];
    const float* ln1w   = (const float*)d_in[5];
    const float* ln1b   = (const float*)d_in[6];
    const float* ln2w   = (const float*)d_in[7];
    const float* ln2b   = (const float*)d_in[8];
    const float* gamma  = (const float*)d_in[9];
    const float* w_off  = (const float*)d_in[10];
    const float* b_off  = (const float*)d_in[11];
    const float* w_aw   = (const float*)d_in[12];
    const float* b_aw   = (const float*)d_in[13];
    const float* w_val  = (const float*)d_in[14];
    const float* b_val  = (const float*)d_in[15];
    const float* w_out  = (const float*)d_in[16];
    const float* b_out  = (const float*)d_in[17];
    float* out = (float*)d_out;

    float *p_sq, *p_skv, *p_val, *p_off, *p_aw, *p_attn;
    cudaGetSymbolAddress((void**)&p_sq,   g_stats_q);
    cudaGetSymbolAddress((void**)&p_skv,  g_stats_kv);
    cudaGetSymbolAddress((void**)&p_val,  g_value);
    cudaGetSymbolAddress((void**)&p_off,  g_offraw);
    cudaGetSymbolAddress((void**)&p_aw,   g_awraw);
    cudaGetSymbolAddress((void**)&p_attn, g_attn);

    // 1) LN row stats
    row_stats<<<RQ  / 8, 256>>>(q,  p_sq,  RQ);
    row_stats<<<RKV / 8, 256>>>(kv, p_skv, RKV);

    // 2) value = LN(kv) @ w_val + b_val   (86016 x 384, K=768)
    gemm_ln<<<dim3(DV / BN, RKV / BM), 256>>>(
        kv, p_skv, ln2w, ln2b, w_val, b_val, p_val, RKV, DV, EMBED, nullptr, nullptr);

    // 3) offraw = LN(q) @ w_off + b_off   (16384 x 288, K=768)
    gemm_ln<<<dim3((NOFF + BN - 1) / BN, RQ / BM), 256>>>(
        q, p_sq, ln1w, ln1b, w_off, b_off, p_off, RQ, NOFF, EMBED, nullptr, nullptr);

    // 4) awraw = LN(q) @ w_aw + b_aw      (16384 x 144, K=768)
    gemm_ln<<<dim3((NAW + BN - 1) / BN, RQ / BM), 256>>>(
        q, p_sq, ln1w, ln1b, w_aw, b_aw, p_aw, RQ, NAW, EMBED, nullptr, nullptr);

    // 5) deformable sampling -> attn (16384 x 384)
    msda_sample<<<RQ, NH * 32>>>(p_off, p_aw, ref, shapes, lstart, p_val, p_attn);

    // 6) out = q + gamma * (attn @ w_out + b_out)   (16384 x 768, K=384)
    gemm_ln<<<dim3(EMBED / BN, RQ / BM), 256>>>(
        p_attn, nullptr, nullptr, nullptr, w_out, b_out, out, RQ, EMBED, DV, q, gamma);
}